// round 16
// baseline (speedup 1.0000x reference)
#include <cuda_runtime.h>
#include <cuda_bf16.h>
#include <cuda_fp8.h>
#include <stdint.h>

#define BATCH 2
#define SEQ   2048
#define DMODEL 2048
#define NHEADS 16
#define DHEAD 128
#define MROWS (BATCH*SEQ)
#define NQKV  (3*DMODEL)

// ---------------- scratch ----------------
__device__ float g_q [ (size_t)MROWS * DMODEL ];
__device__ float g_cc[ (size_t)MROWS * DMODEL ];
__device__ __nv_bfloat16 g_xh [ (size_t)MROWS * DMODEL ];
__device__ __nv_bfloat16 g_xl [ (size_t)MROWS * DMODEL ];
__device__ __nv_bfloat16 g_Wqh[ (size_t)NQKV  * DMODEL ];
__device__ __nv_bfloat16 g_Wql[ (size_t)NQKV  * DMODEL ];
__device__ __nv_bfloat16 g_Woh[ (size_t)DMODEL* DMODEL ];
__device__ __nv_bfloat16 g_qh [ (size_t)MROWS * DMODEL ];
__device__ __nv_bfloat16 g_ql [ (size_t)MROWS * DMODEL ];
__device__ __nv_bfloat16 g_kh [ (size_t)MROWS * DMODEL ];
__device__ __nv_bfloat16 g_kl [ (size_t)MROWS * DMODEL ];
__device__ __nv_bfloat16 g_vh [ (size_t)MROWS * DMODEL ];
__device__ __nv_bfloat16 g_vl [ (size_t)MROWS * DMODEL ];
__device__ __nv_bfloat16 g_zh [ (size_t)MROWS * DMODEL ];
__device__ uint8_t g_x8h [ (size_t)MROWS * DMODEL ];
__device__ uint8_t g_x8l [ (size_t)MROWS * DMODEL ];
__device__ uint8_t g_Wv8h[ (size_t)DMODEL * DMODEL ];
__device__ uint8_t g_Wv8l[ (size_t)DMODEL * DMODEL ];
__device__ uint8_t g_Wo8h[ (size_t)DMODEL * DMODEL ];
__device__ uint8_t g_Wo8l[ (size_t)DMODEL * DMODEL ];
__device__ uint8_t g_z8h [ (size_t)MROWS * DMODEL ];
__device__ uint8_t g_z8l [ (size_t)MROWS * DMODEL ];

// ---------------- helpers ----------------
__device__ __forceinline__ uint32_t smem_u32(const void* p) {
    return (uint32_t)__cvta_generic_to_shared(p);
}
__device__ __forceinline__ void cp16(void* dst, const void* src) {
    asm volatile("cp.async.cg.shared.global [%0], [%1], 16;"
                 :: "r"(smem_u32(dst)), "l"(src));
}
__device__ __forceinline__ void cp_commit() { asm volatile("cp.async.commit_group;"); }
template<int N> __device__ __forceinline__ void cp_wait() {
    asm volatile("cp.async.wait_group %0;" :: "n"(N));
}
__device__ __forceinline__ void ldsm_x4(uint32_t addr, uint32_t& r0, uint32_t& r1,
                                        uint32_t& r2, uint32_t& r3) {
    asm volatile("ldmatrix.sync.aligned.m8n8.x4.shared.b16 {%0,%1,%2,%3}, [%4];"
                 : "=r"(r0), "=r"(r1), "=r"(r2), "=r"(r3) : "r"(addr));
}
__device__ __forceinline__ void ldsm_x4_t(uint32_t addr, uint32_t& r0, uint32_t& r1,
                                          uint32_t& r2, uint32_t& r3) {
    asm volatile("ldmatrix.sync.aligned.m8n8.x4.trans.shared.b16 {%0,%1,%2,%3}, [%4];"
                 : "=r"(r0), "=r"(r1), "=r"(r2), "=r"(r3) : "r"(addr));
}
__device__ __forceinline__ void mma16816(float* d, const uint32_t* a, const uint32_t* b) {
    asm volatile(
        "mma.sync.aligned.m16n8k16.row.col.f32.bf16.bf16.f32 "
        "{%0,%1,%2,%3}, {%4,%5,%6,%7}, {%8,%9}, {%0,%1,%2,%3};"
        : "+f"(d[0]), "+f"(d[1]), "+f"(d[2]), "+f"(d[3])
        : "r"(a[0]), "r"(a[1]), "r"(a[2]), "r"(a[3]), "r"(b[0]), "r"(b[1]));
}
__device__ __forceinline__ void mma8_32(float* d, const uint32_t* a, const uint32_t* b) {
    asm volatile(
        "mma.sync.aligned.m16n8k32.row.col.f32.e4m3.e4m3.f32 "
        "{%0,%1,%2,%3}, {%4,%5,%6,%7}, {%8,%9}, {%0,%1,%2,%3};"
        : "+f"(d[0]), "+f"(d[1]), "+f"(d[2]), "+f"(d[3])
        : "r"(a[0]), "r"(a[1]), "r"(a[2]), "r"(a[3]), "r"(b[0]), "r"(b[1]));
}
__device__ __forceinline__ uint8_t f2e4m3(float x) {
    return (uint8_t)__nv_cvt_float_to_fp8(x, __NV_SATFINITE, __NV_E4M3);
}

// ---------------- splits ----------------
__global__ void split_kernel(const float* __restrict__ in,
                             __nv_bfloat16* __restrict__ h,
                             __nv_bfloat16* __restrict__ l, int n4)
{
    int i = blockIdx.x * blockDim.x + threadIdx.x;
    if (i >= n4) return;
    float4 v = ((const float4*)in)[i];
    __nv_bfloat162 h0 = __floats2bfloat162_rn(v.x, v.y);
    __nv_bfloat162 h1 = __floats2bfloat162_rn(v.z, v.w);
    float2 f0 = __bfloat1622float2(h0);
    float2 f1 = __bfloat1622float2(h1);
    __nv_bfloat162 l0 = __floats2bfloat162_rn(v.x - f0.x, v.y - f0.y);
    __nv_bfloat162 l1 = __floats2bfloat162_rn(v.z - f1.x, v.w - f1.y);
    ((__nv_bfloat162*)h)[2*i]   = h0;
    ((__nv_bfloat162*)h)[2*i+1] = h1;
    ((__nv_bfloat162*)l)[2*i]   = l0;
    ((__nv_bfloat162*)l)[2*i+1] = l1;
}

// h8 = e4m3(a); l8 = e4m3((a - bf16(a)) * 512)
__global__ void split8_kernel(const float* __restrict__ in,
                              uint8_t* __restrict__ h8, uint8_t* __restrict__ l8, int n4)
{
    int i = blockIdx.x * blockDim.x + threadIdx.x;
    if (i >= n4) return;
    float4 v = ((const float4*)in)[i];
    float vv[4] = {v.x, v.y, v.z, v.w};
    uint32_t hw = 0, lw = 0;
#pragma unroll
    for (int j = 0; j < 4; j++) {
        float hi = __bfloat162float(__float2bfloat16(vv[j]));
        hw |= (uint32_t)f2e4m3(vv[j]) << (j * 8);
        lw |= (uint32_t)f2e4m3((vv[j] - hi) * 512.0f) << (j * 8);
    }
    ((uint32_t*)h8)[i] = hw;
    ((uint32_t*)l8)[i] = lw;
}

// ---------------- bf16x3 GEMM (q/k): round-10 proven ----------------
#define GP 40
#define GTSZ (128 * GP)

__global__ __launch_bounds__(256, 2)
void gemm_planes(const __nv_bfloat16* __restrict__ Ah, const __nv_bfloat16* __restrict__ Al,
                 const __nv_bfloat16* __restrict__ Bh, const __nv_bfloat16* __restrict__ Bl,
                 const float* __restrict__ bias,
                 float* __restrict__ C0, float* __restrict__ C1, int K)
{
    extern __shared__ __nv_bfloat16 smg[];
    __nv_bfloat16* sAh = smg;
    __nv_bfloat16* sAl = sAh + 2 * GTSZ;
    __nv_bfloat16* sBh = sAl + 2 * GTSZ;
    __nv_bfloat16* sBl = sBh + 2 * GTSZ;

    const int tid = threadIdx.x, wid = tid >> 5, lane = tid & 31;
    const int wm = wid >> 2, wn = wid & 3;
    const int m0 = blockIdx.y * 128, n0 = blockIdx.x * 128;
    const int lrow = tid >> 1, lcol = (tid & 1) * 16;

    float acc[4][4][4];
#pragma unroll
    for (int i = 0; i < 4; i++)
#pragma unroll
        for (int j = 0; j < 4; j++)
#pragma unroll
            for (int r = 0; r < 4; r++) acc[i][j][r] = 0.f;

    const int iters = K / 32;
    auto load_tile = [&](int t, int st) {
        size_t ga = (size_t)(m0 + lrow) * K + t * 32 + lcol;
        size_t gb = (size_t)(n0 + lrow) * K + t * 32 + lcol;
        size_t so = (size_t)st * GTSZ + lrow * GP + lcol;
        cp16(sAh + so, Ah + ga);  cp16(sAh + so + 8, Ah + ga + 8);
        cp16(sAl + so, Al + ga);  cp16(sAl + so + 8, Al + ga + 8);
        cp16(sBh + so, Bh + gb);  cp16(sBh + so + 8, Bh + gb + 8);
        cp16(sBl + so, Bl + gb);  cp16(sBl + so + 8, Bl + gb + 8);
    };

    load_tile(0, 0); cp_commit();
    for (int it = 0; it < iters; ++it) {
        __syncthreads();
        if (it + 1 < iters) { load_tile(it + 1, (it + 1) & 1); cp_commit(); cp_wait<1>(); }
        else cp_wait<0>();
        __syncthreads();
        const __nv_bfloat16* tAh = sAh + (size_t)(it & 1) * GTSZ;
        const __nv_bfloat16* tAl = sAl + (size_t)(it & 1) * GTSZ;
        const __nv_bfloat16* tBh = sBh + (size_t)(it & 1) * GTSZ;
        const __nv_bfloat16* tBl = sBl + (size_t)(it & 1) * GTSZ;
#pragma unroll
        for (int ks = 0; ks < 2; ks++) {
            const int kk = ks * 16;
            uint32_t afh[4][4], afl[4][4];
#pragma unroll
            for (int mt = 0; mt < 4; mt++) {
                int r = wm * 64 + mt * 16 + (lane & 15);
                int c = kk + ((lane >> 4) * 8);
                ldsm_x4(smem_u32(tAh + r * GP + c), afh[mt][0], afh[mt][1], afh[mt][2], afh[mt][3]);
                ldsm_x4(smem_u32(tAl + r * GP + c), afl[mt][0], afl[mt][1], afl[mt][2], afl[mt][3]);
            }
            uint32_t bfh[4][2], bfl[4][2];
#pragma unroll
            for (int p = 0; p < 2; p++) {
                int r = wn * 32 + p * 16 + (lane & 15);
                int c = kk + ((lane >> 4) * 8);
                uint32_t t0, t1, t2, t3;
                ldsm_x4(smem_u32(tBh + r * GP + c), t0, t1, t2, t3);
                bfh[2*p][0] = t0; bfh[2*p][1] = t2; bfh[2*p+1][0] = t1; bfh[2*p+1][1] = t3;
                ldsm_x4(smem_u32(tBl + r * GP + c), t0, t1, t2, t3);
                bfl[2*p][0] = t0; bfl[2*p][1] = t2; bfl[2*p+1][0] = t1; bfl[2*p+1][1] = t3;
            }
#pragma unroll
            for (int mt = 0; mt < 4; mt++)
#pragma unroll
                for (int nt = 0; nt < 4; nt++) {
                    mma16816(acc[mt][nt], afh[mt], bfh[nt]);
                    mma16816(acc[mt][nt], afh[mt], bfl[nt]);
                    mma16816(acc[mt][nt], afl[mt], bfh[nt]);
                }
        }
    }
#pragma unroll
    for (int mt = 0; mt < 4; mt++)
#pragma unroll
        for (int nt = 0; nt < 4; nt++)
#pragma unroll
            for (int r = 0; r < 4; r++) {
                size_t row = m0 + wm * 64 + mt * 16 + (lane >> 2) + (r >> 1) * 8;
                int    col = n0 + wn * 32 + nt * 8 + (lane & 3) * 2 + (r & 1);
                float v = acc[mt][nt][r] + bias[col];
                if (col < DMODEL) C0[row * (size_t)DMODEL + col] = v;
                else              C1[row * (size_t)DMODEL + (col - DMODEL)] = v;
            }
}

// ---------------- fp8 cross GEMM: Cc = (A8h*B8l + A8l*B8h)/512 ----------------
#define XP 80
#define XPLANE (128 * XP)
#define XSTAGE (4 * XPLANE)

__global__ __launch_bounds__(256, 2)
void gemm_cross8(const uint8_t* __restrict__ A8h, const uint8_t* __restrict__ A8l,
                 const uint8_t* __restrict__ B8h, const uint8_t* __restrict__ B8l,
                 float* __restrict__ Cc, int K)
{
    extern __shared__ char smc[];
    const int tid = threadIdx.x, wid = tid >> 5, lane = tid & 31;
    const int wm = wid >> 2, wn = wid & 3;
    const int m0 = blockIdx.y * 128, n0 = blockIdx.x * 128;

    float acc[4][4][4];
#pragma unroll
    for (int i = 0; i < 4; i++)
#pragma unroll
        for (int j = 0; j < 4; j++)
#pragma unroll
            for (int r = 0; r < 4; r++) acc[i][j][r] = 0.f;

    const int iters = K / 64;
    auto load_slab = [&](int t, int st) {
        char* dst = smc + (size_t)st * XSTAGE;
#pragma unroll
        for (int i = 0; i < 8; i++) {
            int idx = i * 256 + tid;
            int pl = idx >> 9, rem = idx & 511;
            int r = rem >> 2, ch = rem & 3;
            char* d = dst + pl * XPLANE + r * XP + ch * 16;
            const uint8_t* s;
            if (pl == 0)      s = A8h + (size_t)(m0 + r) * K + t * 64 + ch * 16;
            else if (pl == 1) s = A8l + (size_t)(m0 + r) * K + t * 64 + ch * 16;
            else if (pl == 2) s = B8h + (size_t)(n0 + r) * K + t * 64 + ch * 16;
            else              s = B8l + (size_t)(n0 + r) * K + t * 64 + ch * 16;
            cp16(d, s);
        }
    };

    load_slab(0, 0); cp_commit();
    for (int it = 0; it < iters; ++it) {
        __syncthreads();
        if (it + 1 < iters) { load_slab(it + 1, (it + 1) & 1); cp_commit(); cp_wait<1>(); }
        else cp_wait<0>();
        __syncthreads();
        const char* st = smc + (size_t)(it & 1) * XSTAGE;
        const char* pAh = st;
        const char* pAl = st + XPLANE;
        const char* pBh = st + 2 * XPLANE;
        const char* pBl = st + 3 * XPLANE;
#pragma unroll
        for (int ks = 0; ks < 2; ks++) {
            const int kk = ks * 32;   // byte offset of this k32 step
            uint32_t afh[4][4], afl[4][4];
#pragma unroll
            for (int mt = 0; mt < 4; mt++) {
                int r = wm * 64 + mt * 16 + (lane & 15);
                int c = kk + ((lane >> 4) * 16);
                ldsm_x4(smem_u32(pAh + r * XP + c), afh[mt][0], afh[mt][1], afh[mt][2], afh[mt][3]);
                ldsm_x4(smem_u32(pAl + r * XP + c), afl[mt][0], afl[mt][1], afl[mt][2], afl[mt][3]);
            }
            uint32_t bfh[4][2], bfl[4][2];
#pragma unroll
            for (int p = 0; p < 2; p++) {
                int r = wn * 32 + p * 16 + (lane & 15);
                int c = kk + ((lane >> 4) * 16);
                uint32_t t0, t1, t2, t3;
                ldsm_x4(smem_u32(pBh + r * XP + c), t0, t1, t2, t3);
                bfh[2*p][0] = t0; bfh[2*p][1] = t2; bfh[2*p+1][0] = t1; bfh[2*p+1][1] = t3;
                ldsm_x4(smem_u32(pBl + r * XP + c), t0, t1, t2, t3);
                bfl[2*p][0] = t0; bfl[2*p][1] = t2; bfl[2*p+1][0] = t1; bfl[2*p+1][1] = t3;
            }
#pragma unroll
            for (int mt = 0; mt < 4; mt++)
#pragma unroll
                for (int nt = 0; nt < 4; nt++) {
                    mma8_32(acc[mt][nt], afh[mt], bfl[nt]);
                    mma8_32(acc[mt][nt], afl[mt], bfh[nt]);
                }
        }
    }
    const float inv512 = 1.0f / 512.0f;
#pragma unroll
    for (int mt = 0; mt < 4; mt++)
#pragma unroll
        for (int nt = 0; nt < 4; nt++)
#pragma unroll
            for (int rr = 0; rr < 2; rr++) {
                size_t row = m0 + wm * 64 + mt * 16 + (lane >> 2) + rr * 8;
                int    col = n0 + wn * 32 + nt * 8 + (lane & 3) * 2;
                float2 v;
                v.x = acc[mt][nt][2*rr]     * inv512;
                v.y = acc[mt][nt][2*rr + 1] * inv512;
                *(float2*)(Cc + row * (size_t)DMODEL + col) = v;
            }
}

// ---------------- hh GEMM: C = Ah*Bh + Cc + bias (optional v-plane emit) ----
__global__ __launch_bounds__(256, 2)
void gemm_hh(const __nv_bfloat16* __restrict__ Ah, const __nv_bfloat16* __restrict__ Bh,
             const float* __restrict__ bias, const float* __restrict__ Cc,
             float* __restrict__ C0,
             __nv_bfloat16* __restrict__ VH, __nv_bfloat16* __restrict__ VL,
             int K, int emitv)
{
    extern __shared__ __nv_bfloat16 smh[];
    __nv_bfloat16* sAh = smh;
    __nv_bfloat16* sBh = sAh + 2 * GTSZ;

    const int tid = threadIdx.x, wid = tid >> 5, lane = tid & 31;
    const int wm = wid >> 2, wn = wid & 3;
    const int m0 = blockIdx.y * 128, n0 = blockIdx.x * 128;
    const int lrow = tid >> 1, lcol = (tid & 1) * 16;

    float acc[4][4][4];
#pragma unroll
    for (int i = 0; i < 4; i++)
#pragma unroll
        for (int j = 0; j < 4; j++)
#pragma unroll
            for (int r = 0; r < 4; r++) acc[i][j][r] = 0.f;

    const int iters = K / 32;
    auto load_tile = [&](int t, int st) {
        size_t ga = (size_t)(m0 + lrow) * K + t * 32 + lcol;
        size_t gb = (size_t)(n0 + lrow) * K + t * 32 + lcol;
        size_t so = (size_t)st * GTSZ + lrow * GP + lcol;
        cp16(sAh + so, Ah + ga);  cp16(sAh + so + 8, Ah + ga + 8);
        cp16(sBh + so, Bh + gb);  cp16(sBh + so + 8, Bh + gb + 8);
    };

    load_tile(0, 0); cp_commit();
    for (int it = 0; it < iters; ++it) {
        __syncthreads();
        if (it + 1 < iters) { load_tile(it + 1, (it + 1) & 1); cp_commit(); cp_wait<1>(); }
        else cp_wait<0>();
        __syncthreads();
        const __nv_bfloat16* tAh = sAh + (size_t)(it & 1) * GTSZ;
        const __nv_bfloat16* tBh = sBh + (size_t)(it & 1) * GTSZ;
#pragma unroll
        for (int ks = 0; ks < 2; ks++) {
            const int kk = ks * 16;
            uint32_t afh[4][4];
#pragma unroll
            for (int mt = 0; mt < 4; mt++) {
                int r = wm * 64 + mt * 16 + (lane & 15);
                int c = kk + ((lane >> 4) * 8);
                ldsm_x4(smem_u32(tAh + r * GP + c), afh[mt][0], afh[mt][1], afh[mt][2], afh[mt][3]);
            }
            uint32_t bfh[4][2];
#pragma unroll
            for (int p = 0; p < 2; p++) {
                int r = wn * 32 + p * 16 + (lane & 15);
                int c = kk + ((lane >> 4) * 8);
                uint32_t t0, t1, t2, t3;
                ldsm_x4(smem_u32(tBh + r * GP + c), t0, t1, t2, t3);
                bfh[2*p][0] = t0; bfh[2*p][1] = t2; bfh[2*p+1][0] = t1; bfh[2*p+1][1] = t3;
            }
#pragma unroll
            for (int mt = 0; mt < 4; mt++)
#pragma unroll
                for (int nt = 0; nt < 4; nt++)
                    mma16816(acc[mt][nt], afh[mt], bfh[nt]);
        }
    }
#pragma unroll
    for (int mt = 0; mt < 4; mt++)
#pragma unroll
        for (int nt = 0; nt < 4; nt++)
#pragma unroll
            for (int rr = 0; rr < 2; rr++) {
                size_t row = m0 + wm * 64 + mt * 16 + (lane >> 2) + rr * 8;
                int    col = n0 + wn * 32 + nt * 8 + (lane & 3) * 2;
                size_t idx = row * (size_t)DMODEL + col;
                float2 cc = *(const float2*)(Cc + idx);
                float vx = acc[mt][nt][2*rr]     + cc.x + bias[col];
                float vy = acc[mt][nt][2*rr + 1] + cc.y + bias[col + 1];
                *(float2*)(C0 + idx) = make_float2(vx, vy);
                if (emitv) {
                    __nv_bfloat162 hh = __floats2bfloat162_rn(vx, vy);
                    float2 f = __bfloat1622float2(hh);
                    __nv_bfloat162 ll = __floats2bfloat162_rn(vx - f.x, vy - f.y);
                    *(__nv_bfloat162*)(VH + idx) = hh;
                    *(__nv_bfloat162*)(VL + idx) = ll;
                }
            }
}

// ---------------- rmsnorm ----------------
__global__ void rmsnorm_split(const float* __restrict__ qin, const float* __restrict__ kin,
                              __nv_bfloat16* __restrict__ qh, __nv_bfloat16* __restrict__ ql,
                              __nv_bfloat16* __restrict__ kh, __nv_bfloat16* __restrict__ kl,
                              const float* __restrict__ wq, const float* __restrict__ wk)
{
    const float* in;  __nv_bfloat16 *oh, *ol;  const float* w;
    if (blockIdx.y == 0) { in = qin; oh = qh; ol = ql; w = wq; }
    else                 { in = kin; oh = kh; ol = kl; w = wk; }
    size_t base = (size_t)blockIdx.x * DHEAD;
    int t = threadIdx.x;
    float v = in[base + t];
    float ss = v * v;
#pragma unroll
    for (int o = 16; o > 0; o >>= 1) ss += __shfl_xor_sync(0xffffffffu, ss, o);
    __shared__ float sred[4];
    int wrp = t >> 5, lane = t & 31;
    if (lane == 0) sred[wrp] = ss;
    __syncthreads();
    float tot = sred[0] + sred[1] + sred[2] + sred[3];
    float inv = rsqrtf(tot * (1.0f / DHEAD) + 1e-6f);
    float vn = v * inv * w[t];
    __nv_bfloat16 hh = __float2bfloat16(vn);
    oh[base + t] = hh;
    ol[base + t] = __float2bfloat16(vn - __bfloat162float(hh));
}

// ---------------- attention (round-10 best + z8 emit) ----------------
#define QP 136
#define KVK 32
#define KVT (KVK * QP)

__global__ __launch_bounds__(128, 2)
void attn_tc3(const __nv_bfloat16* __restrict__ Qh_g, const __nv_bfloat16* __restrict__ Ql_g,
              const __nv_bfloat16* __restrict__ Kh_g, const __nv_bfloat16* __restrict__ Kl_g,
              const __nv_bfloat16* __restrict__ Vh_g, const __nv_bfloat16* __restrict__ Vl_g,
              __nv_bfloat16* __restrict__ ZH,
              uint8_t* __restrict__ Z8H, uint8_t* __restrict__ Z8L)
{
    extern __shared__ __nv_bfloat16 smx[];
    __nv_bfloat16* Qh = smx;
    __nv_bfloat16* Ql = Qh + 64 * QP;
    __nv_bfloat16* Kh = Ql + 64 * QP;
    __nv_bfloat16* Kl = Kh + 2 * KVT;
    __nv_bfloat16* Vh = Kl + 2 * KVT;
    __nv_bfloat16* Vl = Vh + 2 * KVT;

    const int tid = threadIdx.x, wid = tid >> 5, lane = tid & 31;
    const int b = blockIdx.z, h = blockIdx.y, q0 = blockIdx.x * 64;
    const size_t rowBase = (size_t)b * SEQ;
    const int colBase = h * DHEAD;

    {
        int r = tid >> 1;
        int c0 = (tid & 1) * 64;
        size_t g = (rowBase + q0 + r) * DMODEL + colBase + c0;
#pragma unroll
        for (int i = 0; i < 8; i++) {
            *(uint4*)(Qh + r * QP + c0 + i * 8) = *(const uint4*)(Qh_g + g + i * 8);
            *(uint4*)(Ql + r * QP + c0 + i * 8) = *(const uint4*)(Ql_g + g + i * 8);
        }
    }

    auto load_tile = [&](int jt, int st) {
        int kr0 = jt * KVK;
#pragma unroll
        for (int i = 0; i < 4; i++) {
            int c = i * 128 + tid;
            int r = c >> 4, col = (c & 15) * 8;
            size_t g = (rowBase + kr0 + r) * DMODEL + colBase + col;
            size_t s = (size_t)st * KVT + r * QP + col;
            cp16(Kh + s, Kh_g + g);
            cp16(Kl + s, Kl_g + g);
            cp16(Vh + s, Vh_g + g);
            cp16(Vl + s, Vl_g + g);
        }
    };

    float m_i[2] = {-1e30f, -1e30f};
    float l_i[2] = {0.f, 0.f};
    float o[16][4];
#pragma unroll
    for (int i = 0; i < 16; i++)
#pragma unroll
        for (int r = 0; r < 4; r++) o[i][r] = 0.f;

    load_tile(0, 0); cp_commit();
    const int NT = SEQ / KVK;
    for (int jt = 0; jt < NT; jt++) {
        __syncthreads();
        if (jt + 1 < NT) { load_tile(jt + 1, (jt + 1) & 1); cp_commit(); cp_wait<1>(); }
        else cp_wait<0>();
        __syncthreads();
        const size_t st = (size_t)(jt & 1) * KVT;

        float s[4][4];
#pragma unroll
        for (int i = 0; i < 4; i++)
#pragma unroll
            for (int r = 0; r < 4; r++) s[i][r] = 0.f;
#pragma unroll
        for (int ks = 0; ks < 8; ks++) {
            uint32_t ah[4], al[4];
            {
                int r = wid * 16 + (lane & 15);
                int c = ks * 16 + ((lane >> 4) * 8);
                ldsm_x4(smem_u32(Qh + r * QP + c), ah[0], ah[1], ah[2], ah[3]);
                ldsm_x4(smem_u32(Ql + r * QP + c), al[0], al[1], al[2], al[3]);
            }
#pragma unroll
            for (int p = 0; p < 2; p++) {
                int r = p * 16 + (lane & 15);
                int c = ks * 16 + ((lane >> 4) * 8);
                uint32_t t0, t1, t2, t3;
                uint32_t bh0[2], bh1[2], bl0[2], bl1[2];
                ldsm_x4(smem_u32(Kh + st + r * QP + c), t0, t1, t2, t3);
                bh0[0] = t0; bh0[1] = t2; bh1[0] = t1; bh1[1] = t3;
                ldsm_x4(smem_u32(Kl + st + r * QP + c), t0, t1, t2, t3);
                bl0[0] = t0; bl0[1] = t2; bl1[0] = t1; bl1[1] = t3;
                mma16816(s[2*p],   ah, bh0);
                mma16816(s[2*p],   ah, bl0);
                mma16816(s[2*p],   al, bh0);
                mma16816(s[2*p+1], ah, bh1);
                mma16816(s[2*p+1], ah, bl1);
                mma16816(s[2*p+1], al, bh1);
            }
        }
#pragma unroll
        for (int half = 0; half < 2; half++) {
            float rmax = -1e30f;
#pragma unroll
            for (int nt = 0; nt < 4; nt++)
                rmax = fmaxf(rmax, fmaxf(s[nt][2*half], s[nt][2*half + 1]));
            rmax = fmaxf(rmax, __shfl_xor_sync(0xffffffffu, rmax, 1));
            rmax = fmaxf(rmax, __shfl_xor_sync(0xffffffffu, rmax, 2));
            float mnew = fmaxf(m_i[half], rmax);
            float scale = __expf(m_i[half] - mnew);
            float rs = 0.f;
#pragma unroll
            for (int nt = 0; nt < 4; nt++) {
                float p0 = __expf(s[nt][2*half]     - mnew);
                float p1 = __expf(s[nt][2*half + 1] - mnew);
                s[nt][2*half] = p0; s[nt][2*half + 1] = p1;
                rs += p0 + p1;
            }
            rs += __shfl_xor_sync(0xffffffffu, rs, 1);
            rs += __shfl_xor_sync(0xffffffffu, rs, 2);
            l_i[half] = l_i[half] * scale + rs;
            m_i[half] = mnew;
#pragma unroll
            for (int nt = 0; nt < 16; nt++) {
                o[nt][2*half] *= scale; o[nt][2*half + 1] *= scale;
            }
        }
#pragma unroll
        for (int kk = 0; kk < 2; kk++) {
            uint32_t pah[4], pal[4];
            {
                float v0 = s[2*kk][0],   v1 = s[2*kk][1],   v2 = s[2*kk][2],   v3 = s[2*kk][3];
                float w0 = s[2*kk+1][0], w1 = s[2*kk+1][1], w2 = s[2*kk+1][2], w3 = s[2*kk+1][3];
                __nv_bfloat162 hx; float2 f;
                hx = __floats2bfloat162_rn(v0, v1); f = __bfloat1622float2(hx);
                pah[0] = *(uint32_t*)&hx; { __nv_bfloat162 t = __floats2bfloat162_rn(v0 - f.x, v1 - f.y); pal[0] = *(uint32_t*)&t; }
                hx = __floats2bfloat162_rn(v2, v3); f = __bfloat1622float2(hx);
                pah[1] = *(uint32_t*)&hx; { __nv_bfloat162 t = __floats2bfloat162_rn(v2 - f.x, v3 - f.y); pal[1] = *(uint32_t*)&t; }
                hx = __floats2bfloat162_rn(w0, w1); f = __bfloat1622float2(hx);
                pah[2] = *(uint32_t*)&hx; { __nv_bfloat162 t = __floats2bfloat162_rn(w0 - f.x, w1 - f.y); pal[2] = *(uint32_t*)&t; }
                hx = __floats2bfloat162_rn(w2, w3); f = __bfloat1622float2(hx);
                pah[3] = *(uint32_t*)&hx; { __nv_bfloat162 t = __floats2bfloat162_rn(w2 - f.x, w3 - f.y); pal[3] = *(uint32_t*)&t; }
            }
#pragma unroll
            for (int p = 0; p < 8; p++) {
                int r = kk * 16 + (lane & 15);
                int c = p * 16 + ((lane >> 4) * 8);
                uint32_t vh0[2], vh1[2], vl0[2], vl1[2];
                uint32_t t0, t1, t2, t3;
                ldsm_x4_t(smem_u32(Vh + st + r * QP + c), t0, t1, t2, t3);
                vh0[0] = t0; vh0[1] = t1; vh1[0] = t2; vh1[1] = t3;
                ldsm_x4_t(smem_u32(Vl + st + r * QP + c), t0, t1, t2, t3);
                vl0[0] = t0; vl0[1] = t1; vl1[0] = t2; vl1[1] = t3;
                mma16816(o[2*p],   pah, vh0);
                mma16816(o[2*p],   pah, vl0);
                mma16816(o[2*p],   pal, vh0);
                mma16816(o[2*p+1], pah, vh1);
                mma16816(o[2*p+1], pah, vl1);
                mma16816(o[2*p+1], pal, vh1);
            }
        }
    }

    float invl[2] = {1.f / l_i[0], 1.f / l_i[1]};
#pragma unroll
    for (int half = 0; half < 2; half++) {
        size_t row = rowBase + q0 + wid * 16 + (lane >> 2) + half * 8;
#pragma unroll
        for (int nt = 0; nt < 16; nt++) {
            int col = colBase + nt * 8 + (lane & 3) * 2;
            size_t idx = row * DMODEL + col;
            float vx = o[nt][2*half]     * invl[half];
            float vy = o[nt][2*half + 1] * invl[half];
            __nv_bfloat162 hh = __floats2bfloat162_rn(vx, vy);
            float2 f = __bfloat1622float2(hh);
            *(__nv_bfloat162*)(ZH + idx) = hh;
            uint16_t h8 = (uint16_t)f2e4m3(vx) | ((uint16_t)f2e4m3(vy) << 8);
            uint16_t l8 = (uint16_t)f2e4m3((vx - f.x) * 512.0f)
                        | ((uint16_t)f2e4m3((vy - f.y) * 512.0f) << 8);
            *(uint16_t*)(Z8H + idx) = h8;
            *(uint16_t*)(Z8L + idx) = l8;
        }
    }
}

// ---------------- launcher ----------------
extern "C" void kernel_launch(void* const* d_in, const int* in_sizes, int n_in,
                              void* d_out, int out_size)
{
    const float* x     = (const float*)d_in[0];
    const float* W_qkv = (const float*)d_in[1];
    const float* b_qkv = (const float*)d_in[2];
    const float* W_o   = (const float*)d_in[3];
    const float* b_o   = (const float*)d_in[4];
    const float* wq    = (const float*)d_in[5];
    const float* wk    = (const float*)d_in[6];

    float* out   = (float*)d_out;
    float* k_out = out   + (size_t)MROWS * DMODEL;
    float* v_out = k_out + (size_t)MROWS * DMODEL;

    float *qPtr, *ccPtr;
    __nv_bfloat16 *xh, *xl, *Wqh, *Wql, *Woh;
    __nv_bfloat16 *qh, *ql, *kh, *kl, *vh, *vl, *zh;
    uint8_t *x8h, *x8l, *Wv8h, *Wv8l, *Wo8h, *Wo8l, *z8h, *z8l;
    cudaGetSymbolAddress((void**)&qPtr,  g_q);
    cudaGetSymbolAddress((void**)&ccPtr, g_cc);
    cudaGetSymbolAddress((void**)&xh,  g_xh);  cudaGetSymbolAddress((void**)&xl,  g_xl);
    cudaGetSymbolAddress((void**)&Wqh, g_Wqh); cudaGetSymbolAddress((void**)&Wql, g_Wql);
    cudaGetSymbolAddress((void**)&Woh, g_Woh);
    cudaGetSymbolAddress((void**)&qh,  g_qh);  cudaGetSymbolAddress((void**)&ql,  g_ql);
    cudaGetSymbolAddress((void**)&kh,  g_kh);  cudaGetSymbolAddress((void**)&kl,  g_kl);
    cudaGetSymbolAddress((void**)&vh,  g_vh);  cudaGetSymbolAddress((void**)&vl,  g_vl);
    cudaGetSymbolAddress((void**)&zh,  g_zh);
    cudaGetSymbolAddress((void**)&x8h, g_x8h); cudaGetSymbolAddress((void**)&x8l, g_x8l);
    cudaGetSymbolAddress((void**)&Wv8h,g_Wv8h);cudaGetSymbolAddress((void**)&Wv8l,g_Wv8l);
    cudaGetSymbolAddress((void**)&Wo8h,g_Wo8h);cudaGetSymbolAddress((void**)&Wo8l,g_Wo8l);
    cudaGetSymbolAddress((void**)&z8h, g_z8h); cudaGetSymbolAddress((void**)&z8l, g_z8l);

    // 0) splits
    {
        int n4x = MROWS * DMODEL / 4;
        split_kernel<<<(n4x + 255) / 256, 256>>>(x, xh, xl, n4x);
        int n4q = NQKV * DMODEL / 4;
        split_kernel<<<(n4q + 255) / 256, 256>>>(W_qkv, Wqh, Wql, n4q);
        int n4o = DMODEL * DMODEL / 4;
        // Woh only (hi plane); Wql slot reused as dummy lo sink is NOT allowed -> use g_Wql tail? No: write lo into g_Wql is wrong.
        // W_o hi plane via split8-style: reuse split_kernel writing lo to unused region of g_Wql? Unsafe. Use dedicated: lo plane unused, write into g_Wql is WRONG.
        // Instead: split W_o into Woh + (lo discarded into g_Wql+offset beyond Wq usage? also wrong).
        split_kernel<<<(n4o + 255) / 256, 256>>>(W_o, Woh, (__nv_bfloat16*)z8l /*scratch, overwritten later*/, n4o);
        split8_kernel<<<(n4x + 255) / 256, 256>>>(x, x8h, x8l, n4x);
        split8_kernel<<<(n4o + 255) / 256, 256>>>(W_qkv + (size_t)2 * DMODEL * DMODEL, Wv8h, Wv8l, n4o);
        split8_kernel<<<(n4o + 255) / 256, 256>>>(W_o, Wo8h, Wo8l, n4o);
    }

    int gsm = 8 * GTSZ * (int)sizeof(__nv_bfloat16);      // 81920 B
    int hsm = 4 * GTSZ * (int)sizeof(__nv_bfloat16);      // 40960 B
    int xsm = 2 * XSTAGE;                                 // 81920 B
    cudaFuncSetAttribute(gemm_planes, cudaFuncAttributeMaxDynamicSharedMemorySize, gsm);
    cudaFuncSetAttribute(gemm_cross8, cudaFuncAttributeMaxDynamicSharedMemorySize, xsm);
    cudaFuncSetAttribute(gemm_hh,     cudaFuncAttributeMaxDynamicSharedMemorySize, hsm);

    // 1a) q/k projection (bf16x3), N = 4096
    {
        dim3 grid(4096 / 128, MROWS / 128);
        gemm_planes<<<grid, 256, gsm>>>(xh, xl, Wqh, Wql, b_qkv, qPtr, k_out, DMODEL);
    }
    // 1b) v projection: fp8 cross + bf16 hh (emits v planes)
    {
        dim3 grid(DMODEL / 128, MROWS / 128);
        gemm_cross8<<<grid, 256, xsm>>>(x8h, x8l, Wv8h, Wv8l, ccPtr, DMODEL);
        gemm_hh<<<grid, 256, hsm>>>(xh, Wqh + (size_t)2 * DMODEL * DMODEL,
                                    b_qkv + 2 * DMODEL, ccPtr, v_out, vh, vl, DMODEL, 1);
    }
    // 2) rmsnorm
    {
        dim3 grid(MROWS * NHEADS, 2);
        rmsnorm_split<<<grid, DHEAD>>>(qPtr, k_out, qh, ql, kh, kl, wq, wk);
    }
    // 3) attention (emits zh bf16-hi + z8 planes)
    {
        int smem = (2 * 64 * QP + 8 * KVT) * (int)sizeof(__nv_bfloat16);
        cudaFuncSetAttribute(attn_tc3, cudaFuncAttributeMaxDynamicSharedMemorySize, smem);
        dim3 grid(SEQ / 64, NHEADS, BATCH);
        attn_tc3<<<grid, 128, smem>>>(qh, ql, kh, kl, vh, vl, zh, z8h, z8l);
    }
    // 4) out projection: fp8 cross + bf16 hh
    {
        dim3 grid(DMODEL / 128, MROWS / 128);
        gemm_cross8<<<grid, 256, xsm>>>(z8h, z8l, Wo8h, Wo8l, ccPtr, DMODEL);
        gemm_hh<<<grid, 256, hsm>>>(zh, Woh, b_o, ccPtr, out, nullptr, nullptr, DMODEL, 0);
    }
}